// round 14
// baseline (speedup 1.0000x reference)
#include <cuda_runtime.h>
#include <cuda_fp16.h>
#include <cstdint>

// out[1024,4096] = tanh(x[1024,8192] @ scatter(W[8192,4096]) + bias)
// sm_100 base target (no tcgen05). Converged model: all mma.sync flavors =
// 512 MAC/cyc/SM; R6/R13 GEMM measured at 99.9% of that floor.
// R14: fold the x fp32->fp16 conversion INTO the GEMM (A loaded as fp32,
// cvt.rn.f16x2 in registers pre-MMA; issue slots are idle at rt16). Prep
// shrinks to zero-W only. Pipeline 4->3 stages (A stage doubled), same smem.

#define D_DIM 8192
#define U_DIM 4096
#define B_ROWS 1024

#define MT 128
#define NT 256
#define KC 64
#define APITCHF 72                         // floats per A smem row (288 B)
#define BPITCH 72                          // halves per B smem row (144 B)
#define A_BYT (MT * APITCHF * 4)           // 36864 B
#define B_OFF A_BYT
#define STG_B (A_BYT + NT * BPITCH * 2)    // 73728 B
#define N_STAGES 3
#define SMEM_DYN (N_STAGES * STG_B)        // 221184 B
#define N_ITER (D_DIM / KC)                // 128

#define NW4 ((int)((size_t)U_DIM * D_DIM * 2 / 16))   // uint4 chunks of W

__device__ __half g_W[(size_t)U_DIM * D_DIM];  // Wt[u][d], 64 MB

// ---------------------------------------------------------------- helpers
__device__ __forceinline__ uint32_t smem_u32(const void* p) {
    uint32_t a;
    asm("{ .reg .u64 t; cvta.to.shared.u64 t, %1; cvt.u32.u64 %0, t; }"
        : "=r"(a) : "l"(p));
    return a;
}

__device__ __forceinline__ void mma_f16(float* c, const uint32_t* a, const uint32_t* b) {
    asm volatile(
        "mma.sync.aligned.m16n8k16.row.col.f32.f16.f16.f32 "
        "{%0,%1,%2,%3}, {%4,%5,%6,%7}, {%8,%9}, {%0,%1,%2,%3};"
        : "+f"(c[0]), "+f"(c[1]), "+f"(c[2]), "+f"(c[3])
        : "r"(a[0]), "r"(a[1]), "r"(a[2]), "r"(a[3]), "r"(b[0]), "r"(b[1]));
}

__device__ __forceinline__ uint32_t cvt_h2(float2 v) {
    __half2 h = __floats2half2_rn(v.x, v.y);   // one cvt.rn.f16x2.f32
    return *(uint32_t*)&h;
}

#define CP_ASYNC16(sm, gp) \
    asm volatile("cp.async.cg.shared.global [%0], [%1], 16;" \
                 :: "r"(sm), "l"(gp) : "memory")
#define CP_COMMIT()  asm volatile("cp.async.commit_group;" ::: "memory")
#define CP_WAIT1()   asm volatile("cp.async.wait_group 1;" ::: "memory")

// ---------------------------------------------------------------- pre-passes
__global__ void zerow_kernel(uint4* __restrict__ w) {
    int i = blockIdx.x * blockDim.x + threadIdx.x;
    if (i < NW4) w[i] = make_uint4(0u, 0u, 0u, 0u);
}

__global__ void scatter_kernel(const int2* __restrict__ ind, const float* __restrict__ val,
                               __half* __restrict__ W, int nnz) {
    int i = blockIdx.x * blockDim.x + threadIdx.x;
    if (i < nnz) {
        int2 du = ind[i];  // .x = d (row of dense W), .y = u (col)
        atomicAdd(W + ((size_t)du.y * D_DIM + du.x), __float2half(val[i]));
    }
}

// ---------------------------------------------------------------- GEMM
__global__ void __launch_bounds__(256, 1)
sparse_gemm_kernel(const float* __restrict__ gA,    // x fp32 [1024][8192]
                   const __half* __restrict__ gB,   // g_W [4096][8192]
                   const float* __restrict__ bias,
                   float* __restrict__ out) {
    extern __shared__ char smem[];
    uint32_t sbase = smem_u32(smem);

    const int tid  = threadIdx.x;
    const int lane = tid & 31;
    const int wid  = tid >> 5;
    const int wm   = wid >> 2;        // 0..1 -> rows wm*64
    const int wn   = wid & 3;         // 0..3 -> cols wn*64
    const int mt = blockIdx.x & 7;    // consecutive bx share an N-tile (W L2 reuse)
    const int nt = blockIdx.x >> 3;
    const int m0 = mt * MT, n0 = nt * NT;

    float acc[4][8][4];
#pragma unroll
    for (int f = 0; f < 4; f++)
#pragma unroll
        for (int bf = 0; bf < 8; bf++)
#pragma unroll
            for (int k = 0; k < 4; k++) acc[f][bf][k] = 0.f;

    // stage loader: A 128x64 fp32 (2048 chunks), B 256x64 f16 (2048 chunks)
    auto stage_load = [&](int s, int kt) {
        uint32_t st = sbase + (uint32_t)(s * STG_B);
        const float*  ga = gA + (size_t)m0 * D_DIM + kt * KC;
        const __half* gb = gB + (size_t)n0 * D_DIM + kt * KC;
#pragma unroll
        for (int i = 0; i < 8; i++) {                 // A: 8 chunks/thread
            int ch = tid + i * 256, row = ch >> 4, c = ch & 15;
            CP_ASYNC16(st + (uint32_t)(row * APITCHF + c * 4) * 4u,
                       ga + (size_t)row * D_DIM + c * 4);
        }
#pragma unroll
        for (int i = 0; i < 8; i++) {                 // B: 8 chunks/thread
            int ch = tid + i * 256, row = ch >> 3, c = ch & 7;
            CP_ASYNC16(st + B_OFF + (uint32_t)(row * BPITCH + c * 8) * 2u,
                       gb + (size_t)row * D_DIM + c * 8);
        }
    };

    stage_load(0, 0); CP_COMMIT();
    stage_load(1, 1); CP_COMMIT();

    int s = 0;
    for (int it = 0; it < N_ITER; it++) {
        CP_WAIT1();
        __syncthreads();
        if (it + 2 < N_ITER) {
            int ns = s + 2; if (ns >= N_STAGES) ns -= N_STAGES;
            stage_load(ns, it + 2);
        }
        CP_COMMIT();

        const float*  sA = (const float*)(smem + s * STG_B);
        const __half* sB = (const __half*)(smem + s * STG_B + B_OFF);
        const int rA = wm * 64 + (lane >> 2);
        const int nB = wn * 64 + (lane >> 2);
        const int ktf = (lane & 3) * 2;
#pragma unroll
        for (int kk = 0; kk < 4; kk++) {
            const int k0 = kk * 16 + ktf;
            uint32_t a[4][4];
#pragma unroll
            for (int f = 0; f < 4; f++) {
                const float* ar = sA + (rA + f * 16) * APITCHF + k0;
                a[f][0] = cvt_h2(*(const float2*)(ar));
                a[f][1] = cvt_h2(*(const float2*)(ar + 8 * APITCHF));
                a[f][2] = cvt_h2(*(const float2*)(ar + 8));
                a[f][3] = cvt_h2(*(const float2*)(ar + 8 * APITCHF + 8));
            }
#pragma unroll
            for (int bf = 0; bf < 8; bf++) {
                const __half* br = sB + (nB + bf * 8) * BPITCH + k0;
                uint32_t b[2];
                b[0] = *(const uint32_t*)(br);
                b[1] = *(const uint32_t*)(br + 8);
#pragma unroll
                for (int f = 0; f < 4; f++) mma_f16(acc[f][bf], a[f], b);
            }
        }
        if (++s >= N_STAGES) s = 0;
    }

    // ---- epilogue: bias + tanh, float2 stores ----
#pragma unroll
    for (int f = 0; f < 4; f++) {
        const int r0 = m0 + wm * 64 + f * 16 + (lane >> 2);
#pragma unroll
        for (int bf = 0; bf < 8; bf++) {
            const int cb = n0 + wn * 64 + bf * 8 + 2 * (lane & 3);
            const float b0 = __ldg(bias + cb), b1 = __ldg(bias + cb + 1);
            float2 v0 = {tanhf(acc[f][bf][0] + b0), tanhf(acc[f][bf][1] + b1)};
            float2 v1 = {tanhf(acc[f][bf][2] + b0), tanhf(acc[f][bf][3] + b1)};
            *(float2*)(out + (size_t)r0 * U_DIM + cb) = v0;
            *(float2*)(out + (size_t)(r0 + 8) * U_DIM + cb) = v1;
        }
    }
}

// ---------------------------------------------------------------- host side
extern "C" void kernel_launch(void* const* d_in, const int* in_sizes, int n_in,
                              void* d_out, int out_size) {
    const float* x    = (const float*)d_in[0];
    const float* kv   = (const float*)d_in[1];
    const float* bias = (const float*)d_in[2];
    const int*   ind  = (const int*)d_in[3];
    float* out = (float*)d_out;
    int nnz = in_sizes[1];

    void* wptr = nullptr;
    cudaGetSymbolAddress(&wptr, g_W);

    cudaFuncSetAttribute(sparse_gemm_kernel,
                         cudaFuncAttributeMaxDynamicSharedMemorySize, SMEM_DYN);

    zerow_kernel<<<(NW4 + 255) / 256, 256>>>((uint4*)wptr);

    scatter_kernel<<<(nnz + 255) / 256, 256>>>((const int2*)ind, kv, (__half*)wptr, nnz);

    sparse_gemm_kernel<<<(B_ROWS / MT) * (U_DIM / NT), 256, SMEM_DYN>>>(
        x, (const __half*)wptr, bias, out);
}

// round 15
// speedup vs baseline: 1.0337x; 1.0337x over previous
#include <cuda_runtime.h>
#include <cuda_fp16.h>
#include <cstdint>

// out[1024,4096] = tanh(x[1024,8192] @ scatter(W[8192,4096]) + bias)
// sm_100 base target (no tcgen05). CONVERGED: all mma.sync flavors cap at
// 512 MAC/cyc/SM; this GEMM measures 99.9% of that floor (251.4us). Prep is
// a single fused zero(W)+convert(x) bandwidth pass (22us, L2-resident W);
// scatter is at the random-sector atomic floor (~15us). R14's in-loop cvt
// experiment regressed (+36us) and is reverted: never add mainloop work at
// full tensor-pipe occupancy.

#define D_DIM 8192
#define U_DIM 4096
#define B_ROWS 1024

#define MT 128
#define NT 256
#define KC 64
#define PITCH 72                           // halves per smem row (pad 64->72)
#define A_ST (MT * PITCH)                  // 9216 halves
#define B_ST (NT * PITCH)                  // 18432 halves
#define STG_H (A_ST + B_ST)                // 27648 halves
#define N_STAGES 4
#define SMEM_DYN (N_STAGES * STG_H * 2)    // 221184 B
#define N_ITER (D_DIM / KC)                // 128

#define NW4 ((int)((size_t)U_DIM * D_DIM * 2 / 16))   // uint4 chunks of W: 4194304
#define NX4 (B_ROWS * D_DIM / 4)                      // float4 chunks of x: 2097152

__device__ __half g_W[(size_t)U_DIM * D_DIM];  // Wt[u][d], 64 MB
__device__ __half g_X[(size_t)B_ROWS * D_DIM]; // fp16 x, 16 MB

// ---------------------------------------------------------------- helpers
__device__ __forceinline__ uint32_t smem_u32(const void* p) {
    uint32_t a;
    asm("{ .reg .u64 t; cvta.to.shared.u64 t, %1; cvt.u32.u64 %0, t; }"
        : "=r"(a) : "l"(p));
    return a;
}

__device__ __forceinline__ void mma_f16(float* c, const uint32_t* a, const uint32_t* b) {
    asm volatile(
        "mma.sync.aligned.m16n8k16.row.col.f32.f16.f16.f32 "
        "{%0,%1,%2,%3}, {%4,%5,%6,%7}, {%8,%9}, {%0,%1,%2,%3};"
        : "+f"(c[0]), "+f"(c[1]), "+f"(c[2]), "+f"(c[3])
        : "r"(a[0]), "r"(a[1]), "r"(a[2]), "r"(a[3]), "r"(b[0]), "r"(b[1]));
}

#define CP_ASYNC16(sm, gp) \
    asm volatile("cp.async.cg.shared.global [%0], [%1], 16;" \
                 :: "r"(sm), "l"(gp) : "memory")
#define CP_COMMIT()  asm volatile("cp.async.commit_group;" ::: "memory")
#define CP_WAIT2()   asm volatile("cp.async.wait_group 2;" ::: "memory")

// ---------------------------------------------------------------- fused prep
// blocks [0, NW4/256): zero W.  blocks beyond: convert x to fp16.
__global__ void prep_kernel(const float4* __restrict__ xin, uint2* __restrict__ xout,
                            uint4* __restrict__ w) {
    int i = blockIdx.x * blockDim.x + threadIdx.x;
    if (i < NW4) {
        w[i] = make_uint4(0u, 0u, 0u, 0u);
    } else {
        int j = i - NW4;
        if (j < NX4) {
            float4 v = xin[j];
            __half2 lo = __floats2half2_rn(v.x, v.y);
            __half2 hi = __floats2half2_rn(v.z, v.w);
            xout[j] = make_uint2(*(uint32_t*)&lo, *(uint32_t*)&hi);
        }
    }
}

__global__ void scatter_kernel(const int2* __restrict__ ind, const float* __restrict__ val,
                               __half* __restrict__ W, int nnz) {
    int i = blockIdx.x * blockDim.x + threadIdx.x;
    if (i < nnz) {
        int2 du = ind[i];  // .x = d (row of dense W), .y = u (col)
        atomicAdd(W + ((size_t)du.y * D_DIM + du.x), __float2half(val[i]));
    }
}

// ---------------------------------------------------------------- GEMM (measured 251.4us = HMMA floor)
__global__ void __launch_bounds__(256, 1)
sparse_gemm_kernel(const __half* __restrict__ gA,   // g_X [1024][8192]
                   const __half* __restrict__ gB,   // g_W [4096][8192]
                   const float* __restrict__ bias,
                   float* __restrict__ out) {
    extern __shared__ __half smem[];
    uint32_t sbase = smem_u32(smem);

    const int tid  = threadIdx.x;
    const int lane = tid & 31;
    const int wid  = tid >> 5;
    const int wm   = wid >> 2;        // 0..1 -> rows wm*64
    const int wn   = wid & 3;         // 0..3 -> cols wn*64
    const int mt = blockIdx.x & 7;    // consecutive bx share an N-tile (W L2 reuse)
    const int nt = blockIdx.x >> 3;
    const int m0 = mt * MT, n0 = nt * NT;

    float acc[4][8][4];
#pragma unroll
    for (int f = 0; f < 4; f++)
#pragma unroll
        for (int bf = 0; bf < 8; bf++)
#pragma unroll
            for (int k = 0; k < 4; k++) acc[f][bf][k] = 0.f;

    auto stage_load = [&](int s, int kt) {
        uint32_t sA = sbase + (uint32_t)(s * STG_H) * 2u;
        uint32_t sB = sA + (uint32_t)A_ST * 2u;
        const __half* ga = gA + (size_t)m0 * D_DIM + kt * KC;
        const __half* gb = gB + (size_t)n0 * D_DIM + kt * KC;
#pragma unroll
        for (int i = 0; i < 4; i++) {                 // A: 1024 chunks
            int ch = tid + i * 256, row = ch >> 3, cc = ch & 7;
            CP_ASYNC16(sA + (uint32_t)(row * PITCH + cc * 8) * 2u,
                       ga + (size_t)row * D_DIM + cc * 8);
        }
#pragma unroll
        for (int i = 0; i < 8; i++) {                 // B: 2048 chunks
            int ch = tid + i * 256, row = ch >> 3, cc = ch & 7;
            CP_ASYNC16(sB + (uint32_t)(row * PITCH + cc * 8) * 2u,
                       gb + (size_t)row * D_DIM + cc * 8);
        }
    };

#pragma unroll
    for (int s = 0; s < 3; s++) { stage_load(s, s); CP_COMMIT(); }

    for (int it = 0; it < N_ITER; it++) {
        const int s = it & (N_STAGES - 1);
        CP_WAIT2();
        __syncthreads();
        if (it + 3 < N_ITER) stage_load((it + 3) & (N_STAGES - 1), it + 3);
        CP_COMMIT();

        const __half* sA = smem + s * STG_H;
        const __half* sB = sA + A_ST;
        const int rA = wm * 64 + (lane >> 2);
        const int nB = wn * 64 + (lane >> 2);
        const int kt = (lane & 3) * 2;
#pragma unroll
        for (int kk = 0; kk < 4; kk++) {
            const int k0 = kk * 16 + kt;
            uint32_t a[4][4];
#pragma unroll
            for (int f = 0; f < 4; f++) {
                const __half* ar = sA + (rA + f * 16) * PITCH + k0;
                a[f][0] = *(const uint32_t*)(ar);
                a[f][1] = *(const uint32_t*)(ar + 8 * PITCH);
                a[f][2] = *(const uint32_t*)(ar + 8);
                a[f][3] = *(const uint32_t*)(ar + 8 * PITCH + 8);
            }
#pragma unroll
            for (int bf = 0; bf < 8; bf++) {
                const __half* br = sB + (nB + bf * 8) * PITCH + k0;
                uint32_t b[2];
                b[0] = *(const uint32_t*)(br);
                b[1] = *(const uint32_t*)(br + 8);
#pragma unroll
                for (int f = 0; f < 4; f++) mma_f16(acc[f][bf], a[f], b);
            }
        }
    }

    // ---- epilogue: bias + tanh, float2 stores ----
#pragma unroll
    for (int f = 0; f < 4; f++) {
        const int r0 = m0 + wm * 64 + f * 16 + (lane >> 2);
#pragma unroll
        for (int bf = 0; bf < 8; bf++) {
            const int cb = n0 + wn * 64 + bf * 8 + 2 * (lane & 3);
            const float b0 = __ldg(bias + cb), b1 = __ldg(bias + cb + 1);
            float2 v0 = {tanhf(acc[f][bf][0] + b0), tanhf(acc[f][bf][1] + b1)};
            float2 v1 = {tanhf(acc[f][bf][2] + b0), tanhf(acc[f][bf][3] + b1)};
            *(float2*)(out + (size_t)r0 * U_DIM + cb) = v0;
            *(float2*)(out + (size_t)(r0 + 8) * U_DIM + cb) = v1;
        }
    }
}

// ---------------------------------------------------------------- host side
extern "C" void kernel_launch(void* const* d_in, const int* in_sizes, int n_in,
                              void* d_out, int out_size) {
    const float* x    = (const float*)d_in[0];
    const float* kv   = (const float*)d_in[1];
    const float* bias = (const float*)d_in[2];
    const int*   ind  = (const int*)d_in[3];
    float* out = (float*)d_out;
    int nnz = in_sizes[1];

    void* wptr = nullptr;
    void* xptr = nullptr;
    cudaGetSymbolAddress(&wptr, g_W);
    cudaGetSymbolAddress(&xptr, g_X);

    cudaFuncSetAttribute(sparse_gemm_kernel,
                         cudaFuncAttributeMaxDynamicSharedMemorySize, SMEM_DYN);

    // Fused prep: zero W (4M uint4) + convert x (2M float4) in one launch.
    int total = NW4 + NX4;
    prep_kernel<<<(total + 255) / 256, 256>>>((const float4*)x, (uint2*)xptr,
                                              (uint4*)wptr);

    scatter_kernel<<<(nnz + 255) / 256, 256>>>((const int2*)ind, kv, (__half*)wptr, nnz);

    sparse_gemm_kernel<<<(B_ROWS / MT) * (U_DIM / NT), 256, SMEM_DYN>>>(
        (const __half*)xptr, (const __half*)wptr, bias, out);
}

// round 16
// speedup vs baseline: 1.0401x; 1.0062x over previous
#include <cuda_runtime.h>
#include <cuda_fp16.h>
#include <cstdint>

// out[1024,4096] = tanh(x[1024,8192] @ scatter(W[8192,4096]) + bias)
// sm_100 base target (no tcgen05). CONVERGED GEMM: 251.4us = 100% of the
// 512 MAC/cyc/SM mma.sync cap. R16: dependency-graph reorder — conv(x) is
// independent of W, so fuse it into the scatter launch (disjoint thread
// ranges); zeroW stays a separate prefix. Chain: zeroW -> conv||scatter ->
// GEMM. One fewer launch, conv hidden under atomic latency.

#define D_DIM 8192
#define U_DIM 4096
#define B_ROWS 1024

#define MT 128
#define NT 256
#define KC 64
#define PITCH 72                           // halves per smem row (pad 64->72)
#define A_ST (MT * PITCH)                  // 9216 halves
#define B_ST (NT * PITCH)                  // 18432 halves
#define STG_H (A_ST + B_ST)                // 27648 halves
#define N_STAGES 4
#define SMEM_DYN (N_STAGES * STG_H * 2)    // 221184 B
#define N_ITER (D_DIM / KC)                // 128

#define NW4 ((int)((size_t)U_DIM * D_DIM * 2 / 16))   // uint4 chunks of W: 4194304
#define NX4 (B_ROWS * D_DIM / 4)                      // float4 chunks of x: 2097152

__device__ __half g_W[(size_t)U_DIM * D_DIM];  // Wt[u][d], 64 MB
__device__ __half g_X[(size_t)B_ROWS * D_DIM]; // fp16 x, 16 MB

// ---------------------------------------------------------------- helpers
__device__ __forceinline__ uint32_t smem_u32(const void* p) {
    uint32_t a;
    asm("{ .reg .u64 t; cvta.to.shared.u64 t, %1; cvt.u32.u64 %0, t; }"
        : "=r"(a) : "l"(p));
    return a;
}

__device__ __forceinline__ void mma_f16(float* c, const uint32_t* a, const uint32_t* b) {
    asm volatile(
        "mma.sync.aligned.m16n8k16.row.col.f32.f16.f16.f32 "
        "{%0,%1,%2,%3}, {%4,%5,%6,%7}, {%8,%9}, {%0,%1,%2,%3};"
        : "+f"(c[0]), "+f"(c[1]), "+f"(c[2]), "+f"(c[3])
        : "r"(a[0]), "r"(a[1]), "r"(a[2]), "r"(a[3]), "r"(b[0]), "r"(b[1]));
}

#define CP_ASYNC16(sm, gp) \
    asm volatile("cp.async.cg.shared.global [%0], [%1], 16;" \
                 :: "r"(sm), "l"(gp) : "memory")
#define CP_COMMIT()  asm volatile("cp.async.commit_group;" ::: "memory")
#define CP_WAIT2()   asm volatile("cp.async.wait_group 2;" ::: "memory")

// ---------------------------------------------------------------- pre-passes
__global__ void zerow_kernel(uint4* __restrict__ w) {
    int i = blockIdx.x * blockDim.x + threadIdx.x;
    if (i < NW4) w[i] = make_uint4(0u, 0u, 0u, 0u);
}

// Fused: threads [0, NX4) convert x fp32->fp16; threads [NX4, NX4+nnz)
// scatter-add kernel values into W. The two halves are independent; conv's
// streaming traffic hides under scatter's random-atomic latency.
__global__ void convscatter_kernel(const float4* __restrict__ xin,
                                   uint2* __restrict__ xout,
                                   const int2* __restrict__ ind,
                                   const float* __restrict__ val,
                                   __half* __restrict__ W, int nnz) {
    int i = blockIdx.x * blockDim.x + threadIdx.x;
    if (i < NX4) {
        float4 v = xin[i];
        __half2 lo = __floats2half2_rn(v.x, v.y);
        __half2 hi = __floats2half2_rn(v.z, v.w);
        xout[i] = make_uint2(*(uint32_t*)&lo, *(uint32_t*)&hi);
    } else {
        int j = i - NX4;
        if (j < nnz) {
            int2 du = ind[j];  // .x = d (row of dense W), .y = u (col)
            atomicAdd(W + ((size_t)du.y * D_DIM + du.x), __float2half(val[j]));
        }
    }
}

// ---------------------------------------------------------------- GEMM (measured 251.4us = HMMA floor)
__global__ void __launch_bounds__(256, 1)
sparse_gemm_kernel(const __half* __restrict__ gA,   // g_X [1024][8192]
                   const __half* __restrict__ gB,   // g_W [4096][8192]
                   const float* __restrict__ bias,
                   float* __restrict__ out) {
    extern __shared__ __half smem[];
    uint32_t sbase = smem_u32(smem);

    const int tid  = threadIdx.x;
    const int lane = tid & 31;
    const int wid  = tid >> 5;
    const int wm   = wid >> 2;        // 0..1 -> rows wm*64
    const int wn   = wid & 3;         // 0..3 -> cols wn*64
    const int mt = blockIdx.x & 7;    // consecutive bx share an N-tile (W L2 reuse)
    const int nt = blockIdx.x >> 3;
    const int m0 = mt * MT, n0 = nt * NT;

    float acc[4][8][4];
#pragma unroll
    for (int f = 0; f < 4; f++)
#pragma unroll
        for (int bf = 0; bf < 8; bf++)
#pragma unroll
            for (int k = 0; k < 4; k++) acc[f][bf][k] = 0.f;

    auto stage_load = [&](int s, int kt) {
        uint32_t sA = sbase + (uint32_t)(s * STG_H) * 2u;
        uint32_t sB = sA + (uint32_t)A_ST * 2u;
        const __half* ga = gA + (size_t)m0 * D_DIM + kt * KC;
        const __half* gb = gB + (size_t)n0 * D_DIM + kt * KC;
#pragma unroll
        for (int i = 0; i < 4; i++) {                 // A: 1024 chunks
            int ch = tid + i * 256, row = ch >> 3, cc = ch & 7;
            CP_ASYNC16(sA + (uint32_t)(row * PITCH + cc * 8) * 2u,
                       ga + (size_t)row * D_DIM + cc * 8);
        }
#pragma unroll
        for (int i = 0; i < 8; i++) {                 // B: 2048 chunks
            int ch = tid + i * 256, row = ch >> 3, cc = ch & 7;
            CP_ASYNC16(sB + (uint32_t)(row * PITCH + cc * 8) * 2u,
                       gb + (size_t)row * D_DIM + cc * 8);
        }
    };

#pragma unroll
    for (int s = 0; s < 3; s++) { stage_load(s, s); CP_COMMIT(); }

    for (int it = 0; it < N_ITER; it++) {
        const int s = it & (N_STAGES - 1);
        CP_WAIT2();
        __syncthreads();
        if (it + 3 < N_ITER) stage_load((it + 3) & (N_STAGES - 1), it + 3);
        CP_COMMIT();

        const __half* sA = smem + s * STG_H;
        const __half* sB = sA + A_ST;
        const int rA = wm * 64 + (lane >> 2);
        const int nB = wn * 64 + (lane >> 2);
        const int kt = (lane & 3) * 2;
#pragma unroll
        for (int kk = 0; kk < 4; kk++) {
            const int k0 = kk * 16 + kt;
            uint32_t a[4][4];
#pragma unroll
            for (int f = 0; f < 4; f++) {
                const __half* ar = sA + (rA + f * 16) * PITCH + k0;
                a[f][0] = *(const uint32_t*)(ar);
                a[f][1] = *(const uint32_t*)(ar + 8 * PITCH);
                a[f][2] = *(const uint32_t*)(ar + 8);
                a[f][3] = *(const uint32_t*)(ar + 8 * PITCH + 8);
            }
#pragma unroll
            for (int bf = 0; bf < 8; bf++) {
                const __half* br = sB + (nB + bf * 8) * PITCH + k0;
                uint32_t b[2];
                b[0] = *(const uint32_t*)(br);
                b[1] = *(const uint32_t*)(br + 8);
#pragma unroll
                for (int f = 0; f < 4; f++) mma_f16(acc[f][bf], a[f], b);
            }
        }
    }

    // ---- epilogue: bias + tanh, float2 stores ----
#pragma unroll
    for (int f = 0; f < 4; f++) {
        const int r0 = m0 + wm * 64 + f * 16 + (lane >> 2);
#pragma unroll
        for (int bf = 0; bf < 8; bf++) {
            const int cb = n0 + wn * 64 + bf * 8 + 2 * (lane & 3);
            const float b0 = __ldg(bias + cb), b1 = __ldg(bias + cb + 1);
            float2 v0 = {tanhf(acc[f][bf][0] + b0), tanhf(acc[f][bf][1] + b1)};
            float2 v1 = {tanhf(acc[f][bf][2] + b0), tanhf(acc[f][bf][3] + b1)};
            *(float2*)(out + (size_t)r0 * U_DIM + cb) = v0;
            *(float2*)(out + (size_t)(r0 + 8) * U_DIM + cb) = v1;
        }
    }
}

// ---------------------------------------------------------------- host side
extern "C" void kernel_launch(void* const* d_in, const int* in_sizes, int n_in,
                              void* d_out, int out_size) {
    const float* x    = (const float*)d_in[0];
    const float* kv   = (const float*)d_in[1];
    const float* bias = (const float*)d_in[2];
    const int*   ind  = (const int*)d_in[3];
    float* out = (float*)d_out;
    int nnz = in_sizes[1];

    void* wptr = nullptr;
    void* xptr = nullptr;
    cudaGetSymbolAddress(&wptr, g_W);
    cudaGetSymbolAddress(&xptr, g_X);

    cudaFuncSetAttribute(sparse_gemm_kernel,
                         cudaFuncAttributeMaxDynamicSharedMemorySize, SMEM_DYN);

    zerow_kernel<<<(NW4 + 255) / 256, 256>>>((uint4*)wptr);

    int total = NX4 + nnz;
    convscatter_kernel<<<(total + 255) / 256, 256>>>(
        (const float4*)x, (uint2*)xptr, (const int2*)ind, kv, (__half*)wptr, nnz);

    sparse_gemm_kernel<<<(B_ROWS / MT) * (U_DIM / NT), 256, SMEM_DYN>>>(
        (const __half*)xptr, (const __half*)wptr, bias, out);
}